// round 8
// baseline (speedup 1.0000x reference)
#include <cuda_runtime.h>

// Problem constants
#define B 256
#define N_IN 100          // input retrieval dim
#define R 80              // RETRIEVAL_NUM
#define D 768             // feature dim
#define ROWQ (D / 4)      // 192 float4s per feature row
#define THRESH 0.5f

// Output layout (flattened concatenation, all float32):
//   vis_packed : B*R*D   (rows [0, B*R) of float4 width ROWQ)
//   txt_packed : B*R*D   (rows [B*R, 2*B*R))
//   text_mask  : B*(R+1)
//   img_mask   : B*(R+1)
//   rr_mod     : B*R
//   labels     : B*R
#define OFF_TMASK ((size_t)2 * B * R * D)
#define OFF_IMASK (OFF_TMASK + (size_t)B * (R + 1))
#define OFF_RRMOD (OFF_IMASK + (size_t)B * (R + 1))
#define OFF_LBL   (OFF_RRMOD + (size_t)B * R)

// Fused launch geometry
#define SPLIT 10                                   // blocks per batch
#define THREADS 256
#define PER_BATCH (2 * R * ROWQ)                   // 30720 float4s per batch
#define PER_BLOCK (PER_BATCH / SPLIT)              // 3072 float4s per block
#define ITERS (PER_BLOCK / THREADS)                // 12
#define NROW_HALF ((unsigned)B * R)                // 20480 (vis/txt row split)

// ---------------------------------------------------------------------------
// Single fused kernel. Block (b, s): recompute batch-b compaction in smem,
// block s==0 writes small outputs, all blocks copy their slice of the big
// gathered region.
// ---------------------------------------------------------------------------
__global__ void __launch_bounds__(THREADS)
fused_pack(const float4* __restrict__ vis,
           const float4* __restrict__ txt,
           const float* __restrict__ rrcp,
           const float* __restrict__ labels_in,
           float* __restrict__ out) {
    __shared__ float sh_r[R];
    __shared__ int   sh_src[R];    // global source row (b*N_IN + idx) or -1
    __shared__ int   sh_cnt;
    __shared__ int   sh_all_below;

    const unsigned bid = blockIdx.x;
    const unsigned b = bid / SPLIT;
    const unsigned s = bid - b * SPLIT;
    const unsigned t = threadIdx.x;

    if (t < R) sh_r[t] = rrcp[b * N_IN + t];
    __syncthreads();

    if (t == 0) {
        int cnt = 0;
        int all_below = 1;
        const int base = b * N_IN;
        #pragma unroll 4
        for (int i = 0; i < R; ++i) {
            float r = sh_r[i];
            if (r > THRESH) {                 // binary = 1 (strict >)
                sh_src[cnt] = base + i;
                ++cnt;
            }
            if (r >= THRESH) all_below = 0;   // rr_mod nonzero iff rr >= 0.5
        }
        for (int i = cnt; i < R; ++i) sh_src[i] = -1;
        sh_cnt = cnt;
        sh_all_below = all_below;
    }
    __syncthreads();

    // ---- small outputs (one block per batch) ----
    if (s == 0) {
        const int cnt = sh_cnt;
        if (t < R) {
            float r = sh_r[t];
            float rm = (r < THRESH) ? 0.0f : r;
            if (t == 0 && sh_all_below) rm = 1.0f;
            out[OFF_RRMOD + (size_t)b * R + t] = rm;
            out[OFF_LBL   + (size_t)b * R + t] = labels_in[b * N_IN + t];
        }
        if (t < R + 1) {
            float tm = (t <= cnt) ? 1.0f : 0.0f;
            out[OFF_TMASK + (size_t)b * (R + 1) + t] = tm;
            float im = (b == B - 1) ? tm : 1.0f;
            out[OFF_IMASK + (size_t)b * (R + 1) + t] = im;
        }
    }

    // ---- big gathered copy: this block's slice of batch b's vis+txt ----
    // Local element space e in [0, PER_BATCH): lrow = e/ROWQ in [0, 2R),
    // wh = lrow >= R (txt), j = lrow % R, lane = e % ROWQ.
    float4* out_f4 = (float4*)out;
    const unsigned ebase = s * PER_BLOCK + t;

    #pragma unroll
    for (int g = 0; g < ITERS / 4; ++g) {
        unsigned oidx[4];
        float4 v[4];
        #pragma unroll
        for (int k = 0; k < 4; ++k) {
            unsigned e = ebase + (g * 4 + k) * THREADS;
            unsigned lrow = e / ROWQ;              // const-div -> mul/shift
            unsigned lane = e - lrow * ROWQ;
            unsigned wh = (lrow >= R) ? 1u : 0u;
            unsigned j = lrow - wh * R;
            unsigned orow = (wh ? NROW_HALF : 0u) + b * R + j;
            oidx[k] = orow * ROWQ + lane;
            int src = sh_src[j];
            if (src >= 0) {
                const float4* sp = wh ? txt : vis;
                v[k] = sp[(size_t)src * ROWQ + lane];
            } else {
                v[k] = make_float4(0.0f, 0.0f, 0.0f, 0.0f);
            }
        }
        #pragma unroll
        for (int k = 0; k < 4; ++k) {
            out_f4[oidx[k]] = v[k];
        }
    }
}

// ---------------------------------------------------------------------------
extern "C" void kernel_launch(void* const* d_in, const int* in_sizes, int n_in,
                              void* d_out, int out_size) {
    // Input order per metadata:
    // 0: mean_pooling_vec (unused)
    // 1: merge_text_vec (unused)
    // 2: retrieved_visual_feature_embedding_cls (B,N,1,D)
    // 3: retrieved_textual_feature_embedding   (B,N,1,D)
    // 4: retrieved_label_list (B,N)
    // 5: RRCP (B,N)
    const float* vis    = (const float*)d_in[2];
    const float* txt    = (const float*)d_in[3];
    const float* labels = (const float*)d_in[4];
    const float* rrcp   = (const float*)d_in[5];
    float* out = (float*)d_out;

    fused_pack<<<B * SPLIT, THREADS>>>(
        (const float4*)vis, (const float4*)txt, rrcp, labels, out);
}

// round 9
// speedup vs baseline: 1.1214x; 1.1214x over previous
#include <cuda_runtime.h>

// Problem constants
#define B 256
#define N_IN 100          // input retrieval dim
#define R 80              // RETRIEVAL_NUM
#define D 768             // feature dim
#define ROWQ (D / 4)      // 192 float4s per feature row
#define THRESH 0.5f

// Output layout (flattened concatenation, all float32):
//   vis_packed : B*R*D
//   txt_packed : B*R*D
//   text_mask  : B*(R+1)
//   img_mask   : B*(R+1)
//   rr_mod     : B*R
//   labels     : B*R
#define OFF_TMASK ((size_t)2 * B * R * D)
#define OFF_IMASK (OFF_TMASK + (size_t)B * (R + 1))
#define OFF_RRMOD (OFF_IMASK + (size_t)B * (R + 1))
#define OFF_LBL   (OFF_RRMOD + (size_t)B * R)

// Per-job source table: g_src[b*R + j] = b*N_IN + src_row  (or -1 => zero-fill)
__device__ int g_src[B * R];

// ---------------------------------------------------------------------------
// Kernel 1: warp-parallel metadata. One warp per batch, 4 warps per block.
// Stable compaction via ballot + popc prefix ranks over 3 chunks (32/32/16).
// ---------------------------------------------------------------------------
#define META_WPB 4
__global__ void __launch_bounds__(32 * META_WPB)
build_meta(const float* __restrict__ rrcp,
           const float* __restrict__ labels_in,
           float* __restrict__ out) {
    const int warp = threadIdx.x >> 5;
    const int lane = threadIdx.x & 31;
    const int b = blockIdx.x * META_WPB + warp;
    if (b >= B) return;

    const int base = b * N_IN;
    const unsigned FULL = 0xFFFFFFFFu;

    // chunk reads (chunk2 covers i=64..79, lanes 0..15)
    float r0 = rrcp[base + lane];
    float r1 = rrcp[base + 32 + lane];
    float r2 = (lane < 16) ? rrcp[base + 64 + lane] : 0.0f;

    unsigned m0 = __ballot_sync(FULL, r0 > THRESH);
    unsigned m1 = __ballot_sync(FULL, r1 > THRESH);
    unsigned m2 = __ballot_sync(FULL, (lane < 16) && (r2 > THRESH));

    const int c0 = __popc(m0);
    const int c01 = c0 + __popc(m1);
    const int cnt = c01 + __popc(m2);

    const unsigned below = (1u << lane) - 1u;

    // stable scatter of selected source rows
    if (m0 & (1u << lane)) g_src[b * R + __popc(m0 & below)] = base + lane;
    if (m1 & (1u << lane)) g_src[b * R + c0 + __popc(m1 & below)] = base + 32 + lane;
    if (m2 & (1u << lane)) g_src[b * R + c01 + __popc(m2 & below)] = base + 64 + lane;

    // tail: -1 sentinels
    for (int j = cnt + lane; j < R; j += 32) g_src[b * R + j] = -1;

    // zero_rows: all rr < 0.5  (rr_mod nonzero iff rr >= 0.5)
    unsigned nz = __ballot_sync(FULL, r0 >= THRESH) |
                  __ballot_sync(FULL, r1 >= THRESH) |
                  __ballot_sync(FULL, (lane < 16) && (r2 >= THRESH));
    const int all_below = (nz == 0u);

    // rr_mod + labels (3 chunks)
    {
        float rm0 = (r0 < THRESH) ? 0.0f : r0;
        if (lane == 0 && all_below) rm0 = 1.0f;
        out[OFF_RRMOD + (size_t)b * R + lane] = rm0;
        out[OFF_LBL   + (size_t)b * R + lane] = labels_in[base + lane];

        float rm1 = (r1 < THRESH) ? 0.0f : r1;
        out[OFF_RRMOD + (size_t)b * R + 32 + lane] = rm1;
        out[OFF_LBL   + (size_t)b * R + 32 + lane] = labels_in[base + 32 + lane];

        if (lane < 16) {
            float rm2 = (r2 < THRESH) ? 0.0f : r2;
            out[OFF_RRMOD + (size_t)b * R + 64 + lane] = rm2;
            out[OFF_LBL   + (size_t)b * R + 64 + lane] = labels_in[base + 64 + lane];
        }
    }

    // masks (81 entries): positions lane, 32+lane, 64+lane (lane<17)
    #pragma unroll
    for (int c = 0; c < 3; ++c) {
        int p = c * 32 + lane;
        if (p <= R) {
            float tm = (p <= cnt) ? 1.0f : 0.0f;
            out[OFF_TMASK + (size_t)b * (R + 1) + p] = tm;
            float im = (b == B - 1) ? tm : 1.0f;
            out[OFF_IMASK + (size_t)b * (R + 1) + p] = im;
        }
    }
}

// ---------------------------------------------------------------------------
// Kernel 2: flat gather over the contiguous vis+txt output region.
// 8 independent load->store chains per thread, exact-count launch:
// TOTAL = 7,864,320 f4 = 3840 blocks * 256 threads * 8 iters.
// Streaming hints: every byte touched exactly once.
// ---------------------------------------------------------------------------
#define GATHER_BLOCKS 3840
#define GATHER_THREADS 256
#define GATHER_ITERS 8
#define GATHER_STRIDE ((unsigned)GATHER_BLOCKS * GATHER_THREADS)   // 983,040

__global__ void __launch_bounds__(GATHER_THREADS)
gather_flat(const float4* __restrict__ vis,
            const float4* __restrict__ txt,
            float4* __restrict__ out) {
    const unsigned e0 = blockIdx.x * GATHER_THREADS + threadIdx.x;
    const unsigned NROWJOB = (unsigned)B * R;     // 20480

    unsigned e[GATHER_ITERS];
    int      so[GATHER_ITERS];
    unsigned lane[GATHER_ITERS];
    int      wh[GATHER_ITERS];

    #pragma unroll
    for (int k = 0; k < GATHER_ITERS; ++k) {
        e[k] = e0 + k * GATHER_STRIDE;
        unsigned row = e[k] / ROWQ;               // const-div -> mul/shift
        lane[k] = e[k] - row * ROWQ;
        wh[k] = (row >= NROWJOB);
        unsigned job = row - (wh[k] ? NROWJOB : 0u);
        so[k] = __ldg(&g_src[job]);               // independent table loads
    }

    float4 v[GATHER_ITERS];
    #pragma unroll
    for (int k = 0; k < GATHER_ITERS; ++k) {
        if (so[k] >= 0) {
            const float4* s = wh[k] ? txt : vis;
            v[k] = __ldcs(&s[(size_t)so[k] * ROWQ + lane[k]]);  // 8 chains in flight
        } else {
            v[k] = make_float4(0.0f, 0.0f, 0.0f, 0.0f);
        }
    }

    #pragma unroll
    for (int k = 0; k < GATHER_ITERS; ++k) {
        __stcs(&out[e[k]], v[k]);
    }
}

// ---------------------------------------------------------------------------
extern "C" void kernel_launch(void* const* d_in, const int* in_sizes, int n_in,
                              void* d_out, int out_size) {
    // Input order per metadata:
    // 0: mean_pooling_vec (unused)
    // 1: merge_text_vec (unused)
    // 2: retrieved_visual_feature_embedding_cls (B,N,1,D)
    // 3: retrieved_textual_feature_embedding   (B,N,1,D)
    // 4: retrieved_label_list (B,N)
    // 5: RRCP (B,N)
    const float* vis    = (const float*)d_in[2];
    const float* txt    = (const float*)d_in[3];
    const float* labels = (const float*)d_in[4];
    const float* rrcp   = (const float*)d_in[5];
    float* out = (float*)d_out;

    build_meta<<<B / META_WPB, 32 * META_WPB>>>(rrcp, labels, out);
    gather_flat<<<GATHER_BLOCKS, GATHER_THREADS>>>(
        (const float4*)vis, (const float4*)txt, (float4*)out);
}

// round 10
// speedup vs baseline: 1.1358x; 1.0128x over previous
#include <cuda_runtime.h>

// Problem constants
#define B 256
#define N_IN 100          // input retrieval dim
#define R 80              // RETRIEVAL_NUM
#define D 768             // feature dim
#define ROWQ (D / 4)      // 192 float4s per feature row
#define THRESH 0.5f

// Output layout (flattened concatenation, all float32):
//   vis_packed : B*R*D   (f4 rows [0, B*R))
//   txt_packed : B*R*D   (f4 rows [B*R, 2*B*R))
//   text_mask  : B*(R+1)
//   img_mask   : B*(R+1)
//   rr_mod     : B*R
//   labels     : B*R
#define OFF_TMASK ((size_t)2 * B * R * D)
#define OFF_IMASK (OFF_TMASK + (size_t)B * (R + 1))
#define OFF_RRMOD (OFF_IMASK + (size_t)B * (R + 1))
#define OFF_LBL   (OFF_RRMOD + (size_t)B * R)

// Fused geometry:
//   Per batch: 2*R rows * 6 chunks/row = 960 chunks of 32 float4 (512B).
//   120 warps per batch, 8 chunks per warp (2 groups of 4 independent chains).
//   3840 gather blocks (8 warps each) + 8 meta blocks for small outputs.
#define GATHER_BLOCKS 3840
#define META_BLOCKS 8
#define THREADS 256
#define WPBATCH 120
#define CPR 6                     // chunks per row (192/32)
#define NROW_HALF ((unsigned)B * R)   // 20480

// position of the j-th (0-indexed) set bit of m (assumes it exists)
__device__ __forceinline__ int nth_set_bit(unsigned m, int j) {
    int p = 0, c;
    c = __popc(m & 0xFFFFu); if (j >= c) { j -= c; p = 16; m >>= 16; }
    c = __popc(m & 0xFFu);   if (j >= c) { j -= c; p += 8; m >>= 8; }
    c = __popc(m & 0xFu);    if (j >= c) { j -= c; p += 4; m >>= 4; }
    c = __popc(m & 0x3u);    if (j >= c) { j -= c; p += 2; m >>= 2; }
    c = (int)(m & 1u);       if (j >= c) { p += 1; }
    return p;
}

__global__ void __launch_bounds__(THREADS)
fused_pack(const float4* __restrict__ vis,
           const float4* __restrict__ txt,
           const float* __restrict__ rrcp,
           const float* __restrict__ labels_in,
           float* __restrict__ out) {
    const unsigned FULL = 0xFFFFFFFFu;
    const unsigned blk = blockIdx.x;
    const int lane = threadIdx.x & 31;
    const int warp = threadIdx.x >> 5;

    if (blk < GATHER_BLOCKS) {
        // ---------------- gather path (one batch per warp) ----------------
        const unsigned w = blk * 8 + warp;          // global warp id
        const unsigned b = w / WPBATCH;             // batch
        const unsigned wloc = w - b * WPBATCH;      // 0..119: chunk lane within batch
        const unsigned base = b * N_IN;

        // warp-private compaction: 3 ballots over 80 RRCP values
        float r0 = rrcp[base + lane];
        float r1 = rrcp[base + 32 + lane];
        float r2 = (lane < 16) ? rrcp[base + 64 + lane] : 0.0f;
        unsigned m0 = __ballot_sync(FULL, r0 > THRESH);
        unsigned m1 = __ballot_sync(FULL, r1 > THRESH);
        unsigned m2 = __ballot_sync(FULL, (lane < 16) && (r2 > THRESH));
        const int c0  = __popc(m0);
        const int c01 = c0 + __popc(m1);
        const int cnt = c01 + __popc(m2);

        float4* out_f4 = (float4*)out;

        #pragma unroll
        for (int g = 0; g < 2; ++g) {
            unsigned dst[4];
            float4 v[4];
            #pragma unroll
            for (int k = 0; k < 4; ++k) {
                const unsigned c = wloc + (unsigned)(g * 4 + k) * WPBATCH; // chunk 0..959
                const unsigned lrow = c / CPR;       // 0..159 (warp-uniform)
                const unsigned coff = c - lrow * CPR;
                const unsigned wh = (lrow >= R) ? 1u : 0u;
                const unsigned j = lrow - (wh ? R : 0u);
                const unsigned orow = (wh ? NROW_HALF : 0u) + b * R + j;
                dst[k] = orow * ROWQ + coff * 32 + lane;
                if ((int)j < cnt) {
                    int pos;
                    if ((int)j < c0)       pos = nth_set_bit(m0, (int)j);
                    else if ((int)j < c01) pos = 32 + nth_set_bit(m1, (int)j - c0);
                    else                   pos = 64 + nth_set_bit(m2, (int)j - c01);
                    const float4* s = wh ? txt : vis;
                    v[k] = __ldcs(&s[(size_t)(base + pos) * ROWQ + coff * 32 + lane]);
                } else {
                    v[k] = make_float4(0.0f, 0.0f, 0.0f, 0.0f);
                }
            }
            #pragma unroll
            for (int k = 0; k < 4; ++k) {
                __stcs(&out_f4[dst[k]], v[k]);
            }
        }
    } else {
        // ---------------- small outputs (8 blocks, 4 batches per warp) ----
        const int mb = blk - GATHER_BLOCKS;          // 0..7
        #pragma unroll
        for (int i = 0; i < 4; ++i) {
            const int b = (mb * 8 + warp) * 4 + i;
            const int base = b * N_IN;

            float r0 = rrcp[base + lane];
            float r1 = rrcp[base + 32 + lane];
            float r2 = (lane < 16) ? rrcp[base + 64 + lane] : 0.0f;

            unsigned m0 = __ballot_sync(FULL, r0 > THRESH);
            unsigned m1 = __ballot_sync(FULL, r1 > THRESH);
            unsigned m2 = __ballot_sync(FULL, (lane < 16) && (r2 > THRESH));
            const int cnt = __popc(m0) + __popc(m1) + __popc(m2);

            // zero_rows: all rr < 0.5 (rr_mod nonzero iff rr >= 0.5)
            unsigned nz = __ballot_sync(FULL, r0 >= THRESH) |
                          __ballot_sync(FULL, r1 >= THRESH) |
                          __ballot_sync(FULL, (lane < 16) && (r2 >= THRESH));
            const int all_below = (nz == 0u);

            // rr_mod + labels (chunks at lane, 32+lane, 64+lane[<16])
            float rm0 = (r0 < THRESH) ? 0.0f : r0;
            if (lane == 0 && all_below) rm0 = 1.0f;
            out[OFF_RRMOD + (size_t)b * R + lane] = rm0;
            out[OFF_LBL   + (size_t)b * R + lane] = labels_in[base + lane];

            float rm1 = (r1 < THRESH) ? 0.0f : r1;
            out[OFF_RRMOD + (size_t)b * R + 32 + lane] = rm1;
            out[OFF_LBL   + (size_t)b * R + 32 + lane] = labels_in[base + 32 + lane];

            if (lane < 16) {
                float rm2 = (r2 < THRESH) ? 0.0f : r2;
                out[OFF_RRMOD + (size_t)b * R + 64 + lane] = rm2;
                out[OFF_LBL   + (size_t)b * R + 64 + lane] = labels_in[base + 64 + lane];
            }

            // masks (81 entries)
            #pragma unroll
            for (int cidx = 0; cidx < 3; ++cidx) {
                int p = cidx * 32 + lane;
                if (p <= R) {
                    float tm = (p <= cnt) ? 1.0f : 0.0f;
                    out[OFF_TMASK + (size_t)b * (R + 1) + p] = tm;
                    float im = (b == B - 1) ? tm : 1.0f;
                    out[OFF_IMASK + (size_t)b * (R + 1) + p] = im;
                }
            }
        }
    }
}

// ---------------------------------------------------------------------------
extern "C" void kernel_launch(void* const* d_in, const int* in_sizes, int n_in,
                              void* d_out, int out_size) {
    // Input order per metadata:
    // 0: mean_pooling_vec (unused)
    // 1: merge_text_vec (unused)
    // 2: retrieved_visual_feature_embedding_cls (B,N,1,D)
    // 3: retrieved_textual_feature_embedding   (B,N,1,D)
    // 4: retrieved_label_list (B,N)
    // 5: RRCP (B,N)
    const float* vis    = (const float*)d_in[2];
    const float* txt    = (const float*)d_in[3];
    const float* labels = (const float*)d_in[4];
    const float* rrcp   = (const float*)d_in[5];
    float* out = (float*)d_out;

    fused_pack<<<GATHER_BLOCKS + META_BLOCKS, THREADS>>>(
        (const float4*)vis, (const float4*)txt, rrcp, labels, out);
}